// round 14
// baseline (speedup 1.0000x reference)
#include <cuda_runtime.h>
#include <cuda_fp16.h>
#include <math.h>
#include <stdint.h>

#define FP16 __half
#define KPAD 384

// ---------------- scratch ----------------
__device__ FP16  g_Rh[512 * 130 * KPAD];     // padded R rows, fp16
__device__ FP16  g_Wh[3 * KPAD * 256];       // W[t][k][f] fp16
__device__ float g_part[512 * 2 * 3 * 256];  // per-(b,half) partial m,S,vmax

static __device__ __forceinline__ uint32_t smem_u32(const void* p) {
    uint32_t r;
    asm("{ .reg .u64 t; cvta.to.shared.u64 t, %1; cvt.u32.u64 %0, t; }" : "=r"(r) : "l"(p));
    return r;
}
static __device__ __forceinline__ void cp16(uint32_t dst, const void* src) {
    asm volatile("cp.async.cg.shared.global [%0], [%1], 16;" :: "r"(dst), "l"(src));
}
static __device__ __forceinline__ void mma_fp16(float* c, const uint32_t* a, uint32_t b0, uint32_t b1) {
    asm volatile(
        "mma.sync.aligned.m16n8k16.row.col.f32.f16.f16.f32 "
        "{%0,%1,%2,%3}, {%4,%5,%6,%7}, {%8,%9}, {%0,%1,%2,%3};"
        : "+f"(c[0]), "+f"(c[1]), "+f"(c[2]), "+f"(c[3])
        : "r"(a[0]), "r"(a[1]), "r"(a[2]), "r"(a[3]), "r"(b0), "r"(b1));
}

// ---------------------------------------------------------------------------
// Kernel A: gather, span means, dual softmax, write fp16 R (384-wide rows)
// ---------------------------------------------------------------------------
__global__ void prep_kernel(const int* __restrict__ inputs,
                            const int* __restrict__ e1s_, const int* __restrict__ e1e_,
                            const int* __restrict__ e2s_, const int* __restrict__ e2e_,
                            const int* __restrict__ p1, const int* __restrict__ p2,
                            const float* __restrict__ emb,
                            const float* __restrict__ pos1, const float* __restrict__ pos2)
{
    extern __shared__ float smf[];
    float* we   = smf;                  // [128][101]
    float* emb0 = smf + 12928;
    float* l1   = emb0 + 100;
    float* l2   = l1 + 100;
    float* sc1  = l2 + 100;
    float* sc2  = sc1 + 128;
    float* ine  = sc2 + 128;
    int*   ids  = (int*)(ine + 128);
    int*   q1   = ids + 128;
    int*   q2   = q1 + 128;
    __shared__ float m1s, S1s, m2s, S2s;

    const int b = blockIdx.x;
    const int tid = threadIdx.x;

    if (tid < 128) {
        ids[tid] = inputs[b * 128 + tid];
        q1[tid]  = p1[b * 128 + tid];
        q2[tid]  = p2[b * 128 + tid];
    } else if (tid < 228) {
        emb0[tid - 128] = emb[tid - 128];
    }
    __syncthreads();

    for (int i = tid; i < 128 * 100; i += 256) {
        int l = i / 100, d = i - l * 100;
        we[l * 101 + d] = emb[(long long)ids[l] * 100 + d];
    }
    __syncthreads();

    if (tid < 100) {
        int s1i = e1s_[b], e1i = e1e_[b];
        int s2i = e2s_[b], e2i = e2e_[b];
        float a = 0.f, c = 0.f;
        for (int l = s1i; l <= e1i; ++l) a += we[l * 101 + tid];
        for (int l = s2i; l <= e2i; ++l) c += we[l * 101 + tid];
        l1[tid] = a / (float)(e1i - s1i + 1);
        l2[tid] = c / (float)(e2i - s2i + 1);
    }
    __syncthreads();

    if (tid < 128) {
        float a = 0.f, c = 0.f;
        const float* w = we + tid * 101;
        #pragma unroll 4
        for (int d = 0; d < 100; ++d) { a += w[d] * l1[d]; c += w[d] * l2[d]; }
        sc1[tid] = a; sc2[tid] = c;
    }
    __syncthreads();

    if (tid < 64) {
        const float* sc = (tid < 32) ? sc1 : sc2;
        int lane = tid & 31;
        float m = -1e30f;
        for (int l = lane; l < 128; l += 32) m = fmaxf(m, sc[l]);
        for (int o = 16; o; o >>= 1) m = fmaxf(m, __shfl_xor_sync(0xffffffffu, m, o));
        float s = 0.f;
        for (int l = lane; l < 128; l += 32) s += expf(sc[l] - m);
        for (int o = 16; o; o >>= 1) s += __shfl_xor_sync(0xffffffffu, s, o);
        if (lane == 0) {
            if (tid < 32) { m1s = m; S1s = s; } else { m2s = m; S2s = s; }
        }
    }
    __syncthreads();

    if (tid < 128)
        ine[tid] = 0.5f * (expf(sc1[tid] - m1s) / S1s + expf(sc2[tid] - m2s) / S2s);
    __syncthreads();

    FP16* rh = g_Rh + ((size_t)b * 130 + 1) * KPAD;
    for (int i = tid; i < 128 * KPAD; i += 256) {
        int l = i / KPAD, d = i - l * KPAD;
        float v = 0.f;
        if (d < 350) {
            float s = ine[l];
            if (d < 300) {
                if (l != 0) {
                    int j = d / 100, dd = d - j * 100;
                    int lw = l - 1 + j;
                    v = ((lw < 128) ? we[lw * 101 + dd] : emb0[dd]) * s;
                }
            } else if (d < 325) {
                v = pos1[q1[l] * 25 + (d - 300)] * s;
            } else {
                v = pos2[q2[l] * 25 + (d - 325)] * s;
            }
        }
        rh[(size_t)l * KPAD + d] = __float2half_rn(v);
    }
    for (int d = tid; d < KPAD; d += 256) {
        FP16 z = __float2half_rn(0.f);
        g_Rh[((size_t)b * 130) * KPAD + d] = z;
        g_Rh[((size_t)b * 130 + 129) * KPAD + d] = z;
    }
}

// ---------------------------------------------------------------------------
// Kernel W: conv weights -> [t][k(384)][f(256)] fp16
// ---------------------------------------------------------------------------
__global__ void wsplit_kernel(const float* __restrict__ convw)
{
    int kk = blockIdx.x;      // t*384 + k
    int f  = threadIdx.x;
    int t  = kk / KPAD;
    int k  = kk - t * KPAD;
    float v = (k < 350) ? convw[(size_t)f * 1050 + t * 350 + k] : 0.f;
    g_Wh[(size_t)kk * 256 + f] = __float2half_rn(v);
}

// ---------------------------------------------------------------------------
// Conv half-kernel: grid (2, 512) = (half, b); 256 threads = 8 warps (2m x 4n).
// M=64 (rows half*64..+63), N=256, 18 chunks of k=64, fp16 single-pass.
// 2 smem buffers, 2 CTAs/SM. Epilogue: bias+tanh -> Rc_s, T=Rc.U, partial
// online softmax/maxpool over this CTA's 64 l's -> g_part.
// smem: buf[2] x (A 64x144=9216 + B 64x528=33792) = 86016;
// epilogue overlay: Rc_s[64][257]f32 @0 (65792), Us @65792 (19456),
//                   Ts @85248 (5120) -> SMEM = 90368. 2 CTAs = 180736 OK.
// ---------------------------------------------------------------------------
#define A_STR 144
#define B_STR 528
#define ABUF  9216
#define BUFSZ 43008
#define CONV_SMEM 90368

static __device__ __forceinline__ void load_chunk(uint32_t smb, int q, int bufi,
                                                  int b, int half, int tid)
{
    const int t = q / 6, kc = q - t * 6;
    const int k0 = kc * 64;
    const uint32_t d = smb + bufi * BUFSZ;
    // A: 64 rows x 64 fp16; thread: row=tid>>2, cols (tid&3)*16..+15 (2 cp16)
    {
        int row = tid >> 2, c = (tid & 3) * 16;
        size_t src = ((size_t)(b * 130 + t + half * 64 + row)) * KPAD + k0 + c;
        uint32_t dst = d + row * A_STR + c * 2;
        cp16(dst,      g_Rh + src);
        cp16(dst + 16, g_Rh + src + 8);
    }
    // B: 64 rows x 256 fp16; thread: row=tid>>2, cols (tid&3)*64..+63 (8 cp16)
    {
        int row = tid >> 2, c = (tid & 3) * 64;
        size_t src = ((size_t)(t * KPAD + k0 + row)) * 256 + c;
        uint32_t dst = d + ABUF + row * B_STR + c * 2;
        #pragma unroll
        for (int j = 0; j < 8; ++j)
            cp16(dst + j * 16, g_Wh + src + j * 8);
    }
}

__global__ __launch_bounds__(256, 2) void conv_half_kernel(const float* __restrict__ convb,
                                                           const float* __restrict__ U,
                                                           const float* __restrict__ WL)
{
    extern __shared__ __align__(256) char smc[];
    const uint32_t smb = smem_u32(smc);
    const int tid  = threadIdx.x;
    const int lane = tid & 31;
    const int wid  = tid >> 5;
    const int wm = wid & 1;           // m 0..1
    const int wn = wid >> 1;          // n 0..3
    const int half = blockIdx.x;
    const int b    = blockIdx.y;

    float acc[2][8][4];
    #pragma unroll
    for (int s = 0; s < 2; ++s)
        #pragma unroll
        for (int j = 0; j < 8; ++j)
            #pragma unroll
            for (int x = 0; x < 4; ++x) acc[s][j][x] = 0.f;

    load_chunk(smb, 0, 0, b, half, tid);
    asm volatile("cp.async.commit_group;" ::: "memory");
    load_chunk(smb, 1, 1, b, half, tid);
    asm volatile("cp.async.commit_group;" ::: "memory");

    const uint32_t aAddrBase = smb + (wm * 32 + (lane & 15)) * A_STR + (lane >> 4) * 16;
    const uint32_t bAddrBase = smb + ABUF + ((lane & 7) + ((lane >> 3) & 1) * 8) * B_STR
                                   + (wn * 64 + (lane >> 4) * 8) * 2;

    for (int q = 0; q < 18; ++q) {
        if (q < 17) asm volatile("cp.async.wait_group 1;" ::: "memory");
        else        asm volatile("cp.async.wait_group 0;" ::: "memory");
        __syncthreads();                    // buf[q&1] ready for all warps
        const uint32_t d = (q & 1) * BUFSZ;

        #pragma unroll
        for (int ks = 0; ks < 4; ++ks) {
            uint32_t ah[2][4];
            #pragma unroll
            for (int s = 0; s < 2; ++s) {
                uint32_t addr = aAddrBase + d + (s * 16) * A_STR + ks * 32;
                asm volatile("ldmatrix.sync.aligned.m8n8.x4.shared.b16 {%0,%1,%2,%3}, [%4];"
                             : "=r"(ah[s][0]), "=r"(ah[s][1]), "=r"(ah[s][2]), "=r"(ah[s][3])
                             : "r"(addr));
            }
            #pragma unroll
            for (int i = 0; i < 4; ++i) {
                uint32_t bb[4];
                uint32_t addr = bAddrBase + d + (ks * 16) * B_STR + i * 32;
                asm volatile("ldmatrix.sync.aligned.m8n8.x4.trans.shared.b16 {%0,%1,%2,%3}, [%4];"
                             : "=r"(bb[0]), "=r"(bb[1]), "=r"(bb[2]), "=r"(bb[3])
                             : "r"(addr));
                #pragma unroll
                for (int s = 0; s < 2; ++s) {
                    mma_fp16(acc[s][2 * i],     ah[s], bb[0], bb[1]);
                    mma_fp16(acc[s][2 * i + 1], ah[s], bb[2], bb[3]);
                }
            }
        }
        __syncthreads();                    // all warps done reading buf[q&1]
        if (q + 2 < 18) {
            load_chunk(smb, q + 2, q & 1, b, half, tid);
            asm volatile("cp.async.commit_group;" ::: "memory");
        }
    }

    // ---------------- epilogue ----------------
    float* Rc_s = (float*)smc;                 // [64][257]
    float* Us   = (float*)(smc + 65792);       // [256*19]
    float* Ts   = (float*)(smc + 85248);       // [64][20]

    const int col_base = wn * 64 + (lane & 3) * 2;
    #pragma unroll
    for (int s = 0; s < 2; ++s) {
        int row = wm * 32 + s * 16 + (lane >> 2);
        #pragma unroll
        for (int j = 0; j < 8; ++j) {
            int col = col_base + j * 8;
            float b0 = __ldg(convb + col), b1 = __ldg(convb + col + 1);
            Rc_s[row * 257 + col]           = tanhf(acc[s][j][0] + b0);
            Rc_s[row * 257 + col + 1]       = tanhf(acc[s][j][1] + b1);
            Rc_s[(row + 8) * 257 + col]     = tanhf(acc[s][j][2] + b0);
            Rc_s[(row + 8) * 257 + col + 1] = tanhf(acc[s][j][3] + b1);
        }
    }
    for (int i = tid; i < 4864; i += 256) Us[i] = U[i];
    __syncthreads();

    // T[l][c] = sum_f Rc_s[l][f] * U[f][c]; warp w -> rows w*8..+7 (local l)
    #pragma unroll 1
    for (int r = 0; r < 8; ++r) {
        const int l = wid * 8 + r;
        const float* rcl = Rc_s + l * 257;
        float tac[19];
        #pragma unroll
        for (int c = 0; c < 19; ++c) tac[c] = 0.f;
        #pragma unroll
        for (int i = 0; i < 8; ++i) {
            int f = i * 32 + lane;
            float a = rcl[f];
            const float* up = Us + f * 19;
            #pragma unroll
            for (int c = 0; c < 19; ++c) tac[c] += a * up[c];
        }
        #pragma unroll
        for (int c = 0; c < 19; ++c) {
            float v = tac[c];
            #pragma unroll
            for (int o = 16; o; o >>= 1) v += __shfl_xor_sync(0xffffffffu, v, o);
            if (lane == c) Ts[l * 20 + c] = v;
        }
    }
    __syncthreads();

    // partial online softmax + maxpool over this CTA's 64 l's (thread = g)
    const int g = tid;
    float wl[19];
    #pragma unroll
    for (int c = 0; c < 19; ++c) wl[c] = __ldg(WL + c * 256 + g);

    float m, S, vmax;
    {
        float gg = 0.f;
        #pragma unroll
        for (int c = 0; c < 19; ++c) gg += Ts[c] * wl[c];
        m = gg; S = 1.f; vmax = Rc_s[g];
    }
    for (int l = 1; l < 64; ++l) {
        const float* tl = Ts + l * 20;
        float gg = 0.f;
        #pragma unroll
        for (int c = 0; c < 19; ++c) gg += tl[c] * wl[c];
        float rc = Rc_s[l * 257 + g];
        float m2 = fmaxf(m, gg);
        float c1 = __expf(m - m2), c2 = __expf(gg - m2);
        S = S * c1 + c2;
        vmax = fmaxf(vmax * c1, rc * c2);
        m = m2;
    }
    float* P = g_part + ((size_t)(b * 2 + half)) * 768;
    P[g]       = m;
    P[256 + g] = S;
    P[512 + g] = vmax;
}

// ---------------------------------------------------------------------------
// Combine kernel: merge the two halves per (b,g); also WL passthrough tail.
// ---------------------------------------------------------------------------
__global__ void combine_kernel(const float* __restrict__ WL, float* __restrict__ out)
{
    const int b = blockIdx.x, g = threadIdx.x;
    const float* P0 = g_part + ((size_t)(b * 2)) * 768;
    const float* P1 = P0 + 768;
    float m1 = P0[g], S1 = P0[256 + g], v1 = P0[512 + g];
    float m2 = P1[g], S2 = P1[256 + g], v2 = P1[512 + g];
    float M = fmaxf(m1, m2);
    float c1 = __expf(m1 - M), c2 = __expf(m2 - M);
    float S = S1 * c1 + S2 * c2;
    float V = fmaxf(v1 * c1, v2 * c2);
    out[(size_t)b * 256 + g] = V / S;
    if (b < 19) out[512 * 256 + b * 256 + g] = WL[b * 256 + g];
}

// ---------------------------------------------------------------------------
extern "C" void kernel_launch(void* const* d_in, const int* in_sizes, int n_in,
                              void* d_out, int out_size)
{
    const int*   inputs = (const int*)d_in[0];
    const int*   e1s    = (const int*)d_in[1];
    const int*   e1e    = (const int*)d_in[2];
    const int*   e2s    = (const int*)d_in[3];
    const int*   e2e    = (const int*)d_in[4];
    const int*   p1     = (const int*)d_in[5];
    const int*   p2     = (const int*)d_in[6];
    const float* emb    = (const float*)d_in[7];
    const float* pos1   = (const float*)d_in[8];
    const float* pos2   = (const float*)d_in[9];
    const float* convw  = (const float*)d_in[10];
    const float* convb  = (const float*)d_in[11];
    const float* U      = (const float*)d_in[12];
    const float* WL     = (const float*)d_in[13];
    float* out = (float*)d_out;

    const int PREP_SMEM = 13996 * 4;
    cudaFuncSetAttribute(prep_kernel, cudaFuncAttributeMaxDynamicSharedMemorySize, PREP_SMEM);
    cudaFuncSetAttribute(conv_half_kernel, cudaFuncAttributeMaxDynamicSharedMemorySize, CONV_SMEM);

    prep_kernel<<<512, 256, PREP_SMEM>>>(inputs, e1s, e1e, e2s, e2e, p1, p2, emb, pos1, pos2);
    wsplit_kernel<<<3 * KPAD, 256>>>(convw);
    conv_half_kernel<<<dim3(2, 512), 256, CONV_SMEM>>>(convb, U, WL);
    combine_kernel<<<512, 256>>>(WL, out);
}

// round 15
// speedup vs baseline: 1.0022x; 1.0022x over previous
#include <cuda_runtime.h>
#include <cuda_fp16.h>
#include <math.h>
#include <stdint.h>

#define FP16 __half
#define KPAD 384

// ---------------- scratch ----------------
__device__ FP16 g_Rh[512 * 130 * KPAD];   // padded R rows, fp16
__device__ FP16 g_Wh[3 * KPAD * 256];     // W[t][k][f] fp16

static __device__ __forceinline__ uint32_t smem_u32(const void* p) {
    uint32_t r;
    asm("{ .reg .u64 t; cvta.to.shared.u64 t, %1; cvt.u32.u64 %0, t; }" : "=r"(r) : "l"(p));
    return r;
}
static __device__ __forceinline__ void cp16(uint32_t dst, const void* src) {
    asm volatile("cp.async.cg.shared.global [%0], [%1], 16;" :: "r"(dst), "l"(src));
}
static __device__ __forceinline__ void mma_fp16(float* c, const uint32_t* a, uint32_t b0, uint32_t b1) {
    asm volatile(
        "mma.sync.aligned.m16n8k16.row.col.f32.f16.f16.f32 "
        "{%0,%1,%2,%3}, {%4,%5,%6,%7}, {%8,%9}, {%0,%1,%2,%3};"
        : "+f"(c[0]), "+f"(c[1]), "+f"(c[2]), "+f"(c[3])
        : "r"(a[0]), "r"(a[1]), "r"(a[2]), "r"(a[3]), "r"(b0), "r"(b1));
}

// ---------------------------------------------------------------------------
// Kernel A: gather, span means, dual softmax, write fp16 R (proven R9 code)
// ---------------------------------------------------------------------------
__global__ void prep_kernel(const int* __restrict__ inputs,
                            const int* __restrict__ e1s_, const int* __restrict__ e1e_,
                            const int* __restrict__ e2s_, const int* __restrict__ e2e_,
                            const int* __restrict__ p1, const int* __restrict__ p2,
                            const float* __restrict__ emb,
                            const float* __restrict__ pos1, const float* __restrict__ pos2)
{
    extern __shared__ float smf[];
    float* we   = smf;                  // [128][101]
    float* emb0 = smf + 12928;
    float* l1   = emb0 + 100;
    float* l2   = l1 + 100;
    float* sc1  = l2 + 100;
    float* sc2  = sc1 + 128;
    float* ine  = sc2 + 128;
    int*   ids  = (int*)(ine + 128);
    int*   q1   = ids + 128;
    int*   q2   = q1 + 128;
    __shared__ float m1s, S1s, m2s, S2s;

    const int b = blockIdx.x;
    const int tid = threadIdx.x;

    if (tid < 128) {
        ids[tid] = inputs[b * 128 + tid];
        q1[tid]  = p1[b * 128 + tid];
        q2[tid]  = p2[b * 128 + tid];
    } else if (tid < 228) {
        emb0[tid - 128] = emb[tid - 128];
    }
    __syncthreads();

    for (int i = tid; i < 128 * 100; i += 256) {
        int l = i / 100, d = i - l * 100;
        we[l * 101 + d] = emb[(long long)ids[l] * 100 + d];
    }
    __syncthreads();

    if (tid < 100) {
        int s1i = e1s_[b], e1i = e1e_[b];
        int s2i = e2s_[b], e2i = e2e_[b];
        float a = 0.f, c = 0.f;
        for (int l = s1i; l <= e1i; ++l) a += we[l * 101 + tid];
        for (int l = s2i; l <= e2i; ++l) c += we[l * 101 + tid];
        l1[tid] = a / (float)(e1i - s1i + 1);
        l2[tid] = c / (float)(e2i - s2i + 1);
    }
    __syncthreads();

    if (tid < 128) {
        float a = 0.f, c = 0.f;
        const float* w = we + tid * 101;
        #pragma unroll 4
        for (int d = 0; d < 100; ++d) { a += w[d] * l1[d]; c += w[d] * l2[d]; }
        sc1[tid] = a; sc2[tid] = c;
    }
    __syncthreads();

    if (tid < 64) {
        const float* sc = (tid < 32) ? sc1 : sc2;
        int lane = tid & 31;
        float m = -1e30f;
        for (int l = lane; l < 128; l += 32) m = fmaxf(m, sc[l]);
        for (int o = 16; o; o >>= 1) m = fmaxf(m, __shfl_xor_sync(0xffffffffu, m, o));
        float s = 0.f;
        for (int l = lane; l < 128; l += 32) s += expf(sc[l] - m);
        for (int o = 16; o; o >>= 1) s += __shfl_xor_sync(0xffffffffu, s, o);
        if (lane == 0) {
            if (tid < 32) { m1s = m; S1s = s; } else { m2s = m; S2s = s; }
        }
    }
    __syncthreads();

    if (tid < 128)
        ine[tid] = 0.5f * (expf(sc1[tid] - m1s) / S1s + expf(sc2[tid] - m2s) / S2s);
    __syncthreads();

    FP16* rh = g_Rh + ((size_t)b * 130 + 1) * KPAD;
    for (int i = tid; i < 128 * KPAD; i += 256) {
        int l = i / KPAD, d = i - l * KPAD;
        float v = 0.f;
        if (d < 350) {
            float s = ine[l];
            if (d < 300) {
                if (l != 0) {
                    int j = d / 100, dd = d - j * 100;
                    int lw = l - 1 + j;
                    v = ((lw < 128) ? we[lw * 101 + dd] : emb0[dd]) * s;
                }
            } else if (d < 325) {
                v = pos1[q1[l] * 25 + (d - 300)] * s;
            } else {
                v = pos2[q2[l] * 25 + (d - 325)] * s;
            }
        }
        rh[(size_t)l * KPAD + d] = __float2half_rn(v);
    }
    for (int d = tid; d < KPAD; d += 256) {
        FP16 z = __float2half_rn(0.f);
        g_Rh[((size_t)b * 130) * KPAD + d] = z;
        g_Rh[((size_t)b * 130 + 129) * KPAD + d] = z;
    }
}

// ---------------------------------------------------------------------------
// Kernel W: conv weights -> [t][k(384)][f(256)] fp16
// ---------------------------------------------------------------------------
__global__ void wsplit_kernel(const float* __restrict__ convw)
{
    int kk = blockIdx.x;      // t*384 + k
    int f  = threadIdx.x;
    int t  = kk / KPAD;
    int k  = kk - t * KPAD;
    float v = (k < 350) ? convw[(size_t)f * 1050 + t * 350 + k] : 0.f;
    g_Wh[(size_t)kk * 256 + f] = __float2half_rn(v);
}

// ---------------------------------------------------------------------------
// Conv kernel: one CTA per b; 1024 threads = 32 warps (4m x 8n), warp tile
// 32x32. M=128 N=256, 18 chunks of k=64, fp16 single-pass, 3 buffers,
// ONE __syncthreads per chunk. Fused epilogue: bias+tanh -> Rc_s, T=Rc.U,
// head (softmax over l in 4 quarters + combine) -> out; WL tail for b<19.
// smem: 3 x (A 128x144=18432 + B 64x528=33792) = 156672;
// epilogue overlay: Rc_s[128][260] @0 (133120), Us @133120 (19456),
//                   Ts[128][20] @152576 (10240) -> 162816 total.
// partials overlay Us after T phase (3 x 1024 floats = 12288 <= 19456).
// ---------------------------------------------------------------------------
#define A_STR 144
#define B_STR 528
#define ABUF  18432
#define BUFSZ 52224
#define CONV_SMEM 162816

static __device__ __forceinline__ void load_chunk(uint32_t smb, int q, int bufi,
                                                  int b, int tid)
{
    const int t = q / 6, kc = q - t * 6;
    const int k0 = kc * 64;
    const uint32_t d = smb + bufi * BUFSZ;
    // A: 128 rows x 64 fp16; thread: row=tid>>3, cols (tid&7)*8 (1 cp16)
    {
        int row = tid >> 3, c = (tid & 7) * 8;
        size_t src = ((size_t)(b * 130 + t + row)) * KPAD + k0 + c;
        cp16(d + row * A_STR + c * 2, g_Rh + src);
    }
    // B: 64 rows x 256 fp16; thread: row=tid>>4, cols (tid&15)*16 (2 cp16)
    {
        int row = tid >> 4, c = (tid & 15) * 16;
        size_t src = ((size_t)(t * KPAD + k0 + row)) * 256 + c;
        uint32_t dst = d + ABUF + row * B_STR + c * 2;
        cp16(dst,      g_Wh + src);
        cp16(dst + 16, g_Wh + src + 8);
    }
}

__global__ __launch_bounds__(1024, 1) void conv_fused_kernel(const float* __restrict__ convb,
                                                             const float* __restrict__ U,
                                                             const float* __restrict__ WL,
                                                             float* __restrict__ out)
{
    extern __shared__ __align__(256) char smc[];
    const uint32_t smb = smem_u32(smc);
    const int tid  = threadIdx.x;
    const int lane = tid & 31;
    const int wid  = tid >> 5;
    const int wm = wid & 3;           // m 0..3 (32-row tiles)
    const int wn = wid >> 2;          // n 0..7 (32-col tiles)
    const int b  = blockIdx.x;

    // WL passthrough tail
    if (b < 19 && tid < 256) out[512 * 256 + b * 256 + tid] = WL[b * 256 + tid];

    float acc[2][4][4];
    #pragma unroll
    for (int s = 0; s < 2; ++s)
        #pragma unroll
        for (int j = 0; j < 4; ++j)
            #pragma unroll
            for (int x = 0; x < 4; ++x) acc[s][j][x] = 0.f;

    load_chunk(smb, 0, 0, b, tid);
    asm volatile("cp.async.commit_group;" ::: "memory");
    load_chunk(smb, 1, 1, b, tid);
    asm volatile("cp.async.commit_group;" ::: "memory");

    const uint32_t aAddrBase = smb + (wm * 32 + (lane & 15)) * A_STR + (lane >> 4) * 16;
    const uint32_t bAddrBase = smb + ABUF + ((lane & 7) + ((lane >> 3) & 1) * 8) * B_STR
                                   + (wn * 32 + (lane >> 4) * 8) * 2;

    int bufi = 0;
    for (int q = 0; q < 18; ++q) {
        if (q < 16) asm volatile("cp.async.wait_group 1;" ::: "memory");
        else        asm volatile("cp.async.wait_group 0;" ::: "memory");
        __syncthreads();
        if (q + 2 < 18) {
            int nb = bufi + 2; if (nb >= 3) nb -= 3;
            load_chunk(smb, q + 2, nb, b, tid);
            asm volatile("cp.async.commit_group;" ::: "memory");
        }
        const uint32_t d = bufi * BUFSZ;

        #pragma unroll
        for (int ks = 0; ks < 4; ++ks) {
            uint32_t ah[2][4];
            #pragma unroll
            for (int s = 0; s < 2; ++s) {
                uint32_t addr = aAddrBase + d + (s * 16) * A_STR + ks * 32;
                asm volatile("ldmatrix.sync.aligned.m8n8.x4.shared.b16 {%0,%1,%2,%3}, [%4];"
                             : "=r"(ah[s][0]), "=r"(ah[s][1]), "=r"(ah[s][2]), "=r"(ah[s][3])
                             : "r"(addr));
            }
            #pragma unroll
            for (int i = 0; i < 2; ++i) {
                uint32_t bb[4];
                uint32_t addr = bAddrBase + d + (ks * 16) * B_STR + i * 32;
                asm volatile("ldmatrix.sync.aligned.m8n8.x4.trans.shared.b16 {%0,%1,%2,%3}, [%4];"
                             : "=r"(bb[0]), "=r"(bb[1]), "=r"(bb[2]), "=r"(bb[3])
                             : "r"(addr));
                #pragma unroll
                for (int s = 0; s < 2; ++s) {
                    mma_fp16(acc[s][2 * i],     ah[s], bb[0], bb[1]);
                    mma_fp16(acc[s][2 * i + 1], ah[s], bb[2], bb[3]);
                }
            }
        }
        if (++bufi >= 3) bufi -= 3;
    }
    __syncthreads();    // mainloop done; smem becomes epilogue scratch

    // ---------------- fused epilogue ----------------
    float* Rc_s = (float*)smc;                 // [128][260]
    float* Us   = (float*)(smc + 133120);      // [256*19]
    float* Ts   = (float*)(smc + 152576);      // [128][20]
    float* Pm   = Us;                          // [4][256] after T phase
    float* Ps   = Us + 1024;
    float* Pv   = Us + 2048;

    const int col_base = wn * 32 + (lane & 3) * 2;
    #pragma unroll
    for (int s = 0; s < 2; ++s) {
        int row = wm * 32 + s * 16 + (lane >> 2);
        #pragma unroll
        for (int j = 0; j < 4; ++j) {
            int col = col_base + j * 8;
            float b0 = __ldg(convb + col), b1 = __ldg(convb + col + 1);
            Rc_s[row * 260 + col]           = tanhf(acc[s][j][0] + b0);
            Rc_s[row * 260 + col + 1]       = tanhf(acc[s][j][1] + b1);
            Rc_s[(row + 8) * 260 + col]     = tanhf(acc[s][j][2] + b0);
            Rc_s[(row + 8) * 260 + col + 1] = tanhf(acc[s][j][3] + b1);
        }
    }
    for (int i = tid; i < 4864; i += 1024) Us[i] = U[i];
    __syncthreads();

    // T[l][c] = sum_f Rc_s[l][f] * U[f][c]; warp w -> rows w*4..+3
    #pragma unroll 1
    for (int r = 0; r < 4; ++r) {
        const int l = wid * 4 + r;
        const float* rcl = Rc_s + l * 260;
        float tac[19];
        #pragma unroll
        for (int c = 0; c < 19; ++c) tac[c] = 0.f;
        #pragma unroll
        for (int i = 0; i < 8; ++i) {
            int f = i * 32 + lane;
            float a = rcl[f];
            const float* up = Us + f * 19;
            #pragma unroll
            for (int c = 0; c < 19; ++c) tac[c] += a * up[c];
        }
        #pragma unroll
        for (int c = 0; c < 19; ++c) {
            float v = tac[c];
            #pragma unroll
            for (int o = 16; o; o >>= 1) v += __shfl_xor_sync(0xffffffffu, v, o);
            if (lane == c) Ts[l * 20 + c] = v;
        }
    }
    __syncthreads();

    // head: per-g online softmax over l + maxpool, split into 4 quarters
    const int g = tid & 255;
    const int quarter = tid >> 8;       // 0..3, l in [q*32, q*32+32)
    float wl[19];
    #pragma unroll
    for (int c = 0; c < 19; ++c) wl[c] = __ldg(WL + c * 256 + g);

    const int l0 = quarter * 32;
    float m, S, vmax;
    {
        const float* tl = Ts + l0 * 20;
        float gg = 0.f;
        #pragma unroll
        for (int c = 0; c < 19; ++c) gg += tl[c] * wl[c];
        m = gg; S = 1.f; vmax = Rc_s[l0 * 260 + g];
    }
    for (int l = l0 + 1; l < l0 + 32; ++l) {
        const float* tl = Ts + l * 20;
        float gg = 0.f;
        #pragma unroll
        for (int c = 0; c < 19; ++c) gg += tl[c] * wl[c];
        float rc = Rc_s[l * 260 + g];
        float m2 = fmaxf(m, gg);
        float c1 = __expf(m - m2), c2 = __expf(gg - m2);
        S = S * c1 + c2;
        vmax = fmaxf(vmax * c1, rc * c2);
        m = m2;
    }
    __syncthreads();    // Ts/Us reads done before Pm overlay writes
    Pm[quarter * 256 + g] = m;
    Ps[quarter * 256 + g] = S;
    Pv[quarter * 256 + g] = vmax;
    __syncthreads();
    if (quarter == 0) {
        float M = m, Sc, V;
        #pragma unroll
        for (int qq = 1; qq < 4; ++qq) M = fmaxf(M, Pm[qq * 256 + g]);
        float c0 = __expf(m - M);
        Sc = S * c0; V = vmax * c0;
        #pragma unroll
        for (int qq = 1; qq < 4; ++qq) {
            float cq = __expf(Pm[qq * 256 + g] - M);
            Sc += Ps[qq * 256 + g] * cq;
            V = fmaxf(V, Pv[qq * 256 + g] * cq);
        }
        out[(size_t)b * 256 + g] = V / Sc;
    }
}

// ---------------------------------------------------------------------------
extern "C" void kernel_launch(void* const* d_in, const int* in_sizes, int n_in,
                              void* d_out, int out_size)
{
    const int*   inputs = (const int*)d_in[0];
    const int*   e1s    = (const int*)d_in[1];
    const int*   e1e    = (const int*)d_in[2];
    const int*   e2s    = (const int*)d_in[3];
    const int*   e2e    = (const int*)d_in[4];
    const int*   p1     = (const int*)d_in[5];
    const int*   p2     = (const int*)d_in[6];
    const float* emb    = (const float*)d_in[7];
    const float* pos1   = (const float*)d_in[8];
    const float* pos2   = (const float*)d_in[9];
    const float* convw  = (const float*)d_in[10];
    const float* convb  = (const float*)d_in[11];
    const float* U      = (const float*)d_in[12];
    const float* WL     = (const float*)d_in[13];
    float* out = (float*)d_out;

    const int PREP_SMEM = 13996 * 4;
    cudaFuncSetAttribute(prep_kernel, cudaFuncAttributeMaxDynamicSharedMemorySize, PREP_SMEM);
    cudaFuncSetAttribute(conv_fused_kernel, cudaFuncAttributeMaxDynamicSharedMemorySize, CONV_SMEM);

    prep_kernel<<<512, 256, PREP_SMEM>>>(inputs, e1s, e1e, e2s, e2e, p1, p2, emb, pos1, pos2);
    wsplit_kernel<<<3 * KPAD, 256>>>(convw);
    conv_fused_kernel<<<512, 1024, CONV_SMEM>>>(convb, U, WL, out);
}

// round 16
// speedup vs baseline: 1.3550x; 1.3521x over previous
#include <cuda_runtime.h>
#include <cuda_fp16.h>
#include <math.h>
#include <stdint.h>

#define FP16 __half
#define KPAD 384

// ---------------- scratch ----------------
__device__ FP16 g_Rh[512 * 130 * KPAD];   // padded R rows, fp16
__device__ FP16 g_Wh[3 * KPAD * 256];     // W[t][k][f] fp16

static __device__ __forceinline__ uint32_t smem_u32(const void* p) {
    uint32_t r;
    asm("{ .reg .u64 t; cvta.to.shared.u64 t, %1; cvt.u32.u64 %0, t; }" : "=r"(r) : "l"(p));
    return r;
}
static __device__ __forceinline__ void cp16(uint32_t dst, const void* src) {
    asm volatile("cp.async.cg.shared.global [%0], [%1], 16;" :: "r"(dst), "l"(src));
}
static __device__ __forceinline__ void mma_fp16(float* c, const uint32_t* a, uint32_t b0, uint32_t b1) {
    asm volatile(
        "mma.sync.aligned.m16n8k16.row.col.f32.f16.f16.f32 "
        "{%0,%1,%2,%3}, {%4,%5,%6,%7}, {%8,%9}, {%0,%1,%2,%3};"
        : "+f"(c[0]), "+f"(c[1]), "+f"(c[2]), "+f"(c[3])
        : "r"(a[0]), "r"(a[1]), "r"(a[2]), "r"(a[3]), "r"(b0), "r"(b1));
}

// ---------------------------------------------------------------------------
// Kernel A: prep — warp-per-row, no div/mod in hot loops, half2 stores
// ---------------------------------------------------------------------------
__global__ void prep_kernel(const int* __restrict__ inputs,
                            const int* __restrict__ e1s_, const int* __restrict__ e1e_,
                            const int* __restrict__ e2s_, const int* __restrict__ e2e_,
                            const int* __restrict__ p1, const int* __restrict__ p2,
                            const float* __restrict__ emb,
                            const float* __restrict__ pos1, const float* __restrict__ pos2)
{
    extern __shared__ float smf[];
    float* we   = smf;                  // [128][101]
    float* emb0 = smf + 12928;
    float* l1   = emb0 + 100;
    float* l2   = l1 + 100;
    float* sc1  = l2 + 100;
    float* sc2  = sc1 + 128;
    float* ine  = sc2 + 128;
    int*   ids  = (int*)(ine + 128);
    int*   q1   = ids + 128;
    int*   q2   = q1 + 128;
    __shared__ float m1s, S1s, m2s, S2s;

    const int b = blockIdx.x;
    const int tid = threadIdx.x;
    const int lane = tid & 31;
    const int wid  = tid >> 5;

    if (tid < 128) {
        ids[tid] = inputs[b * 128 + tid];
        q1[tid]  = p1[b * 128 + tid];
        q2[tid]  = p2[b * 128 + tid];
    } else if (tid < 228) {
        emb0[tid - 128] = emb[tid - 128];
    }
    __syncthreads();

    // gather: warp per row
    for (int l = wid; l < 128; l += 8) {
        const float* src = emb + (long long)ids[l] * 100;
        float* dst = we + l * 101;
        #pragma unroll
        for (int d = lane; d < 100; d += 32) dst[d] = src[d];
    }
    __syncthreads();

    if (tid < 100) {
        int s1i = e1s_[b], e1i = e1e_[b];
        int s2i = e2s_[b], e2i = e2e_[b];
        float a = 0.f, c = 0.f;
        for (int l = s1i; l <= e1i; ++l) a += we[l * 101 + tid];
        for (int l = s2i; l <= e2i; ++l) c += we[l * 101 + tid];
        l1[tid] = a / (float)(e1i - s1i + 1);
        l2[tid] = c / (float)(e2i - s2i + 1);
    }
    __syncthreads();

    if (tid < 128) {
        float a = 0.f, c = 0.f;
        const float* w = we + tid * 101;
        #pragma unroll 4
        for (int d = 0; d < 100; ++d) { a += w[d] * l1[d]; c += w[d] * l2[d]; }
        sc1[tid] = a; sc2[tid] = c;
    }
    __syncthreads();

    if (tid < 64) {
        const float* sc = (tid < 32) ? sc1 : sc2;
        int ln = tid & 31;
        float m = -1e30f;
        for (int l = ln; l < 128; l += 32) m = fmaxf(m, sc[l]);
        for (int o = 16; o; o >>= 1) m = fmaxf(m, __shfl_xor_sync(0xffffffffu, m, o));
        float s = 0.f;
        for (int l = ln; l < 128; l += 32) s += __expf(sc[l] - m);
        for (int o = 16; o; o >>= 1) s += __shfl_xor_sync(0xffffffffu, s, o);
        if (ln == 0) {
            if (tid < 32) { m1s = m; S1s = s; } else { m2s = m; S2s = s; }
        }
    }
    __syncthreads();

    if (tid < 128)
        ine[tid] = 0.5f * (__expf(sc1[tid] - m1s) / S1s + __expf(sc2[tid] - m2s) / S2s);
    __syncthreads();

    // R write: warp per row, paired half2 stores, no div/mod
    FP16* rb = g_Rh + ((size_t)b * 130 + 1) * KPAD;
    for (int l = wid; l < 128; l += 8) {
        const float s = ine[l];
        const float sm = (l == 0) ? 0.f : s;
        FP16* row = rb + (size_t)l * KPAD;
        #pragma unroll
        for (int j = 0; j < 3; ++j) {
            int lw = l - 1 + j;
            const float* srcrow = (l != 0 && lw < 128) ? (we + lw * 101) : emb0;
            {
                int p = lane;                       // pairs 0..31
                float v0 = srcrow[2 * p] * sm;
                float v1 = srcrow[2 * p + 1] * sm;
                *(__half2*)(row + j * 100 + 2 * p) = __floats2half2_rn(v0, v1);
            }
            if (lane < 18) {                        // pairs 32..49
                int p = 32 + lane;
                float v0 = srcrow[2 * p] * sm;
                float v1 = srcrow[2 * p + 1] * sm;
                *(__half2*)(row + j * 100 + 2 * p) = __floats2half2_rn(v0, v1);
            }
        }
        if (lane < 25) {
            row[300 + lane] = __float2half_rn(pos1[q1[l] * 25 + lane] * s);
            row[325 + lane] = __float2half_rn(pos2[q2[l] * 25 + lane] * s);
        }
        if (lane < 17) {                            // pad cols 350..383
            *(__half2*)(row + 350 + 2 * lane) = __floats2half2_rn(0.f, 0.f);
        }
    }
    // zero pad rows 0 and 129
    for (int d = tid; d < KPAD; d += 256) {
        FP16 z = __float2half_rn(0.f);
        g_Rh[((size_t)b * 130) * KPAD + d] = z;
        g_Rh[((size_t)b * 130 + 129) * KPAD + d] = z;
    }
}

// ---------------------------------------------------------------------------
// Kernel W: conv weights -> [t][k(384)][f(256)] fp16
// ---------------------------------------------------------------------------
__global__ void wsplit_kernel(const float* __restrict__ convw)
{
    int kk = blockIdx.x;      // t*384 + k
    int f  = threadIdx.x;
    int t  = kk / KPAD;
    int k  = kk - t * KPAD;
    float v = (k < 350) ? convw[(size_t)f * 1050 + t * 350 + k] : 0.f;
    g_Wh[(size_t)kk * 256 + f] = __float2half_rn(v);
}

// ---------------------------------------------------------------------------
// Conv (R9 proven config + zero-group skip + WL tail): one CTA per b.
// 512 thr = 16 warps (4m x 4n), warp tile 32x64, M=128 N=256.
// 18 chunks of k=64 (3 taps x 6); chunk kc==5 skips ks>=2 (pure zero pad).
// 3 smem buffers, ONE sync per chunk. Fused epilogue: bias+tanh -> Rc_s,
// T=Rc.U, head (2-half online softmax + combine) -> out.
// smem: 3 x (A 128x144=18432 + B 64x528=33792) = 156672;
// epilogue overlay: Rc_s[128][260] @0, Us @133120, Ts @152576 -> 162816.
// ---------------------------------------------------------------------------
#define BUFSZ 52224
#define A_STR 144
#define B_STR 528
#define B_OFF  18432
#define CONV_SMEM 162816

static __device__ __forceinline__ void conv_load(uint32_t smb, int q, int bufi, int b, int tid)
{
    const int t = q / 6, kc = q - t * 6;
    const int k0 = kc * 64;
    const uint32_t d = smb + bufi * BUFSZ;
    // A: 128 rows x 64 fp16: thread row=tid>>2, cols (tid&3)*16..+15 (2 cp16)
    {
        int am = tid >> 2, ac = (tid & 3) * 16;
        size_t src = ((size_t)(b * 130 + t + am)) * KPAD + k0 + ac;
        uint32_t dst = d + am * A_STR + ac * 2;
        cp16(dst,      g_Rh + src);
        cp16(dst + 16, g_Rh + src + 8);
    }
    // B: 64 k-rows x 256 fp16: thread row=tid>>3, cols (tid&7)*32..+31 (4 cp16)
    {
        int bk = tid >> 3, bn = (tid & 7) * 32;
        size_t src = ((size_t)(t * KPAD + k0 + bk)) * 256 + bn;
        uint32_t dst = d + B_OFF + bk * B_STR + bn * 2;
        cp16(dst,      g_Wh + src);
        cp16(dst + 16, g_Wh + src + 8);
        cp16(dst + 32, g_Wh + src + 16);
        cp16(dst + 48, g_Wh + src + 24);
    }
}

__global__ __launch_bounds__(512, 1) void conv_fused_kernel(const float* __restrict__ convb,
                                                            const float* __restrict__ U,
                                                            const float* __restrict__ WL,
                                                            float* __restrict__ out)
{
    extern __shared__ __align__(256) char smc[];
    const uint32_t smb = smem_u32(smc);
    const int tid = threadIdx.x;
    const int lane = tid & 31;
    const int wid  = tid >> 5;
    const int wm = wid & 3;           // m 0..3
    const int wn = wid >> 2;          // n 0..3
    const int b  = blockIdx.x;

    // WL passthrough tail
    if (b < 19 && tid < 256) out[512 * 256 + b * 256 + tid] = WL[b * 256 + tid];

    float acc[2][8][4];
    #pragma unroll
    for (int s = 0; s < 2; ++s)
        #pragma unroll
        for (int j = 0; j < 8; ++j)
            #pragma unroll
            for (int x = 0; x < 4; ++x) acc[s][j][x] = 0.f;

    conv_load(smb, 0, 0, b, tid);
    asm volatile("cp.async.commit_group;" ::: "memory");
    conv_load(smb, 1, 1, b, tid);
    asm volatile("cp.async.commit_group;" ::: "memory");

    const uint32_t aAddrBase = smb + (wm * 32 + (lane & 15)) * A_STR + (lane >> 4) * 16;
    const uint32_t bAddrBase = smb + B_OFF + ((lane & 7) + ((lane >> 3) & 1) * 8) * B_STR
                                   + (wn * 64 + (lane >> 4) * 8) * 2;

    int bufi = 0;
    for (int q = 0; q < 18; ++q) {
        if (q < 16) asm volatile("cp.async.wait_group 1;" ::: "memory");
        else        asm volatile("cp.async.wait_group 0;" ::: "memory");
        __syncthreads();
        if (q + 2 < 18) {
            int nb = bufi + 2; if (nb >= 3) nb -= 3;
            conv_load(smb, q + 2, nb, b, tid);
            asm volatile("cp.async.commit_group;" ::: "memory");
        }
        const uint32_t d = bufi * BUFSZ;
        const int kc = q - (q / 6) * 6;
        const bool shortc = (kc == 5);    // k 352..383 pure zero padding

        #pragma unroll
        for (int ks = 0; ks < 4; ++ks) {
            if (shortc && ks >= 2) continue;
            uint32_t ah[2][4];
            #pragma unroll
            for (int s = 0; s < 2; ++s) {
                uint32_t addr = aAddrBase + d + (s * 16) * A_STR + ks * 32;
                asm volatile("ldmatrix.sync.aligned.m8n8.x4.shared.b16 {%0,%1,%2,%3}, [%4];"
                             : "=r"(ah[s][0]), "=r"(ah[s][1]), "=r"(ah[s][2]), "=r"(ah[s][3])
                             : "r"(addr));
            }
            #pragma unroll
            for (int i = 0; i < 4; ++i) {
                uint32_t bb[4];
                uint32_t addr = bAddrBase + d + (ks * 16) * B_STR + i * 32;
                asm volatile("ldmatrix.sync.aligned.m8n8.x4.trans.shared.b16 {%0,%1,%2,%3}, [%4];"
                             : "=r"(bb[0]), "=r"(bb[1]), "=r"(bb[2]), "=r"(bb[3])
                             : "r"(addr));
                #pragma unroll
                for (int s = 0; s < 2; ++s) {
                    mma_fp16(acc[s][2 * i],     ah[s], bb[0], bb[1]);
                    mma_fp16(acc[s][2 * i + 1], ah[s], bb[2], bb[3]);
                }
            }
        }
        if (++bufi >= 3) bufi -= 3;
    }
    __syncthreads();    // mainloop done; buffers become epilogue scratch

    // ---------------- fused epilogue ----------------
    float* Rc_s = (float*)smc;                 // [128][260]
    float* Us   = (float*)(smc + 133120);      // [256*19]
    float* Ts   = (float*)(smc + 152576);      // [128][20]
    float* Pm   = Us;                          // partial combine reuse
    float* Ps   = Us + 256;
    float* Pv   = Us + 512;

    const int col_base = wn * 64 + (lane & 3) * 2;
    #pragma unroll
    for (int s = 0; s < 2; ++s) {
        int row = wm * 32 + s * 16 + (lane >> 2);
        #pragma unroll
        for (int j = 0; j < 8; ++j) {
            int col = col_base + j * 8;
            float b0 = __ldg(convb + col), b1 = __ldg(convb + col + 1);
            Rc_s[row * 260 + col]           = tanhf(acc[s][j][0] + b0);
            Rc_s[row * 260 + col + 1]       = tanhf(acc[s][j][1] + b1);
            Rc_s[(row + 8) * 260 + col]     = tanhf(acc[s][j][2] + b0);
            Rc_s[(row + 8) * 260 + col + 1] = tanhf(acc[s][j][3] + b1);
        }
    }
    for (int i = tid; i < 4864; i += 512) Us[i] = U[i];
    __syncthreads();

    // T[l][c] = sum_f Rc_s[l][f] * U[f][c]; warp w -> rows w*8..+7
    #pragma unroll 1
    for (int r = 0; r < 8; ++r) {
        const int l = wid * 8 + r;
        const float* rcl = Rc_s + l * 260;
        float tac[19];
        #pragma unroll
        for (int c = 0; c < 19; ++c) tac[c] = 0.f;
        #pragma unroll
        for (int i = 0; i < 8; ++i) {
            int f = i * 32 + lane;
            float a = rcl[f];
            const float* up = Us + f * 19;
            #pragma unroll
            for (int c = 0; c < 19; ++c) tac[c] += a * up[c];
        }
        #pragma unroll
        for (int c = 0; c < 19; ++c) {
            float v = tac[c];
            #pragma unroll
            for (int o = 16; o; o >>= 1) v += __shfl_xor_sync(0xffffffffu, v, o);
            if (lane == c) Ts[l * 20 + c] = v;
        }
    }
    __syncthreads();

    // head: per-g online softmax over l + maxpool, two halves + combine
    const int g = tid & 255;
    const int half = tid >> 8;
    float wl[19];
    #pragma unroll
    for (int c = 0; c < 19; ++c) wl[c] = __ldg(WL + c * 256 + g);

    const int l0 = half * 64;
    float m, S, vmax;
    {
        const float* tl = Ts + l0 * 20;
        float gg = 0.f;
        #pragma unroll
        for (int c = 0; c < 19; ++c) gg += tl[c] * wl[c];
        m = gg; S = 1.f; vmax = Rc_s[l0 * 260 + g];
    }
    for (int l = l0 + 1; l < l0 + 64; ++l) {
        const float* tl = Ts + l * 20;
        float gg = 0.f;
        #pragma unroll
        for (int c = 0; c < 19; ++c) gg += tl[c] * wl[c];
        float rc = Rc_s[l * 260 + g];
        float m2 = fmaxf(m, gg);
        float c1 = __expf(m - m2), c2 = __expf(gg - m2);
        S = S * c1 + c2;
        vmax = fmaxf(vmax * c1, rc * c2);
        m = m2;
    }
    __syncthreads();
    if (half == 1) { Pm[g] = m; Ps[g] = S; Pv[g] = vmax; }
    __syncthreads();
    if (half == 0) {
        float m2 = Pm[g], S2 = Ps[g], v2 = Pv[g];
        float M = fmaxf(m, m2);
        float c1 = __expf(m - M), c2 = __expf(m2 - M);
        float Sc = S * c1 + S2 * c2;
        float V  = fmaxf(vmax * c1, v2 * c2);
        out[(size_t)b * 256 + g] = V / Sc;
    }
}

// ---------------------------------------------------------------------------
extern "C" void kernel_launch(void* const* d_in, const int* in_sizes, int n_in,
                              void* d_out, int out_size)
{
    const int*   inputs = (const int*)d_in[0];
    const int*   e1s    = (const int*)d_in[1];
    const int*   e1e    = (const int*)d_in[2];
    const int*   e2s    = (const int*)d_in[3];
    const int*   e2e    = (const int*)d_in[4];
    const int*   p1     = (const int*)d_in[5];
    const int*   p2     = (const int*)d_in[6];
    const float* emb    = (const float*)d_in[7];
    const float* pos1   = (const float*)d_in[8];
    const float* pos2   = (const float*)d_in[9];
    const float* convw  = (const float*)d_in[10];
    const float* convb  = (const float*)d_in[11];
    const float* U      = (const float*)d_in[12];
    const float* WL     = (const float*)d_in[13];
    float* out = (float*)d_out;

    const int PREP_SMEM = 13996 * 4;
    cudaFuncSetAttribute(prep_kernel, cudaFuncAttributeMaxDynamicSharedMemorySize, PREP_SMEM);
    cudaFuncSetAttribute(conv_fused_kernel, cudaFuncAttributeMaxDynamicSharedMemorySize, CONV_SMEM);

    prep_kernel<<<512, 256, PREP_SMEM>>>(inputs, e1s, e1e, e2s, e2e, p1, p2, emb, pos1, pos2);
    wsplit_kernel<<<3 * KPAD, 256>>>(convw);
    conv_fused_kernel<<<512, 512, CONV_SMEM>>>(convb, U, WL, out);
}